// round 14
// baseline (speedup 1.0000x reference)
#include <cuda_runtime.h>
#include <math.h>
#include <stdint.h>

// Problem shape: B=2, S=4096, H=1024, M=B*S=8192
#define BDIM 2
#define SDIM 4096
#define HDIM 1024
#define MDIM 8192

#define KST 64            // K per smem stage
#define KFF 40            // k-range on FFMA pipe (62.5%; matches 8.6:5.3 TF/s)
#define PADX 132          // floats per smem k-row
#define TILEF (KST * PADX)         // floats per tile (A or B)
#define STGF (2 * TILEF)           // floats per stage (A + B)
#define SMEM_BYTES (2 * STGF * 4)  // 2 stages = 135168 B

// Scratch
__device__ float g_wqt[(size_t)HDIM * HDIM];   // Wq^T
__device__ float g_G[(size_t)HDIM * HDIM];     // Wq^T * Wk
__device__ float g_H[(size_t)HDIM * HDIM];     // Wo * Wv
__device__ float g_T[(size_t)MDIM * HDIM];     // X * G
__device__ float g_U[(size_t)MDIM * HDIM];     // P * X
__device__ float g_s[(size_t)BDIM * SDIM * SDIM];
__device__ float g_c[MDIM];
__device__ float g_u[HDIM];
__device__ float g_upart[32][HDIM];
__device__ float g_d[HDIM];

// ---------------- helpers ----------------
__device__ __forceinline__ uint32_t tf32hi(float x) {
    uint32_t y;
    asm("cvt.rna.tf32.f32 %0, %1;" : "=r"(y) : "f"(x));
    return y;
}
__device__ __forceinline__ float u2f(uint32_t u) { return __uint_as_float(u); }

__device__ __forceinline__ void mma8(float* d, const uint32_t* a, uint32_t b0, uint32_t b1) {
    asm volatile(
        "mma.sync.aligned.m16n8k8.row.col.f32.tf32.tf32.f32 "
        "{%0,%1,%2,%3}, {%4,%5,%6,%7}, {%8,%9}, {%0,%1,%2,%3};\n"
        : "+f"(d[0]), "+f"(d[1]), "+f"(d[2]), "+f"(d[3])
        : "r"(a[0]), "r"(a[1]), "r"(a[2]), "r"(a[3]), "r"(b0), "r"(b1));
}

// ---------------------------------------------------------------------------
// FFMA part: k in [0, KFF). mma-fragment-layout accumulators.
// Warp tile 32(m) x 64(n). Lane (r=lane>>2, c=lane&3) owns rows {base+r, +8},
// cols {2c, 2c+1} of each 16x8 mma tile.
// ---------------------------------------------------------------------------
__device__ __forceinline__ void ffma_part(
    const float* __restrict__ As, const float* __restrict__ Bs,
    int wm, int wn, int r, int c, float acc[2][8][4])
{
    #pragma unroll 4
    for (int k = 0; k < KFF; ++k) {
        const float* ar = As + k * PADX + wm + r;
        const float* br = Bs + k * PADX + wn + 2 * c;
        float a00 = ar[0],  a01 = ar[8];
        float a10 = ar[16], a11 = ar[24];
        #pragma unroll
        for (int nt = 0; nt < 8; nt++) {
            float2 b = *reinterpret_cast<const float2*>(br + 8 * nt);
            acc[0][nt][0] += a00 * b.x; acc[0][nt][1] += a00 * b.y;
            acc[0][nt][2] += a01 * b.x; acc[0][nt][3] += a01 * b.y;
            acc[1][nt][0] += a10 * b.x; acc[1][nt][1] += a10 * b.y;
            acc[1][nt][2] += a11 * b.x; acc[1][nt][3] += a11 * b.y;
        }
    }
}

// ---------------------------------------------------------------------------
// MMA part: k in [KFF, KST), 3 chunks of k8, tf32x3 (hh + hl + lh).
// Full 3-term split: accuracy anchor 2e-5 (validated round 11).
// ---------------------------------------------------------------------------
__device__ __forceinline__ void mma_part(
    const float* __restrict__ As, const float* __restrict__ Bs,
    int wm, int wn, int r, int c, float acc[2][8][4])
{
    #pragma unroll
    for (int ks = 0; ks < (KST - KFF) / 8; ++ks) {
        const int k = KFF + ks * 8;
        const float* a0 = As + (k + c) * PADX + wm + r;
        const float* a1 = As + (k + c + 4) * PADX + wm + r;
        uint32_t ah[2][4], al[2][4];
        #pragma unroll
        for (int mt = 0; mt < 2; mt++) {
            float s0 = a0[mt * 16], s1 = a0[mt * 16 + 8];
            float s2 = a1[mt * 16], s3 = a1[mt * 16 + 8];
            ah[mt][0] = tf32hi(s0); ah[mt][1] = tf32hi(s1);
            ah[mt][2] = tf32hi(s2); ah[mt][3] = tf32hi(s3);
            al[mt][0] = tf32hi(s0 - u2f(ah[mt][0]));
            al[mt][1] = tf32hi(s1 - u2f(ah[mt][1]));
            al[mt][2] = tf32hi(s2 - u2f(ah[mt][2]));
            al[mt][3] = tf32hi(s3 - u2f(ah[mt][3]));
        }
        const float* b0p = Bs + (k + c) * PADX + wn + r;
        const float* b1p = Bs + (k + c + 4) * PADX + wn + r;
        #pragma unroll
        for (int nt = 0; nt < 8; nt++) {
            float t0 = b0p[8 * nt], t1 = b1p[8 * nt];
            uint32_t bh0 = tf32hi(t0), bh1 = tf32hi(t1);
            uint32_t bl0 = tf32hi(t0 - u2f(bh0)), bl1 = tf32hi(t1 - u2f(bh1));
            #pragma unroll
            for (int mt = 0; mt < 2; mt++) {
                mma8(acc[mt][nt], ah[mt], bh0, bh1);  // hi*hi
                mma8(acc[mt][nt], ah[mt], bl0, bl1);  // hi*lo
                mma8(acc[mt][nt], al[mt], bh0, bh1);  // lo*hi
            }
        }
    }
}

// ---------------------------------------------------------------------------
// Hybrid dual-pipe GEMM, register-prefetch double-buffered smem.
// BT=true: B is [N,K] (NT); BT=false: B is [K,N] (NN).
// CTA tile 128x128, 256 threads, 8 warps (4m x 2n of 32x64 warp tiles).
// Pipe stagger by (wid & 4): each SMSP (wid%4) holds one warp from {0-3} and
// one from {4-7}, so one ffma-phase and one mma-phase warp coexist per SMSP.
// ---------------------------------------------------------------------------
template <bool BT>
__global__ __launch_bounds__(256, 1)
void hgemm(const float* __restrict__ A, const float* __restrict__ B,
           const float* __restrict__ bias, float* __restrict__ C,
           int M, int N, int K, float alpha,
           long long sA, long long sB, long long sC, long long sBias)
{
    extern __shared__ float sm[];

    A += (long long)blockIdx.z * sA;
    B += (long long)blockIdx.z * sB;
    C += (long long)blockIdx.z * sC;
    if (bias) bias += (long long)blockIdx.z * sBias;

    const int tid  = threadIdx.x;
    const int lane = tid & 31;
    const int wid  = tid >> 5;
    const int r = lane >> 2;
    const int c = lane & 3;
    const int wm = (wid & 3) * 32;
    const int wn = (wid >> 2) * 64;

    const long long m0 = (long long)blockIdx.y * 128;
    const long long n0 = (long long)blockIdx.x * 128;

    // loader mappings
    const int arow = tid >> 1;          // 0..127
    const int akb  = (tid & 1) * 32;    // 0 or 32
    const int bkr  = tid >> 2;          // 0..63 (NN B rows)
    const int bnc  = (tid & 3) * 32;    // 0..96

    const float* ApA = A + (m0 + arow) * K + akb;
    const float* ApB = BT ? (B + (n0 + arow) * K + akb)
                          : (B + (long long)bkr * N + n0 + bnc);

    float acc[2][8][4];
    #pragma unroll
    for (int i = 0; i < 2; i++)
        #pragma unroll
        for (int j = 0; j < 8; j++)
            #pragma unroll
            for (int q = 0; q < 4; q++) acc[i][j][q] = 0.f;

    const int nt = K / KST;
    float4 va[8], vb[8];

    // prologue: stage 0 -> regs -> smem buffer 0
    #pragma unroll
    for (int i = 0; i < 8; i++) {
        va[i] = *reinterpret_cast<const float4*>(ApA + 4 * i);
        vb[i] = *reinterpret_cast<const float4*>(ApB + 4 * i);
    }
    {
        float* As0 = sm;
        float* Bs0 = sm + TILEF;
        #pragma unroll
        for (int i = 0; i < 8; i++) {
            As0[(akb + 4 * i + 0) * PADX + arow] = va[i].x;
            As0[(akb + 4 * i + 1) * PADX + arow] = va[i].y;
            As0[(akb + 4 * i + 2) * PADX + arow] = va[i].z;
            As0[(akb + 4 * i + 3) * PADX + arow] = va[i].w;
        }
        if (BT) {
            #pragma unroll
            for (int i = 0; i < 8; i++) {
                Bs0[(akb + 4 * i + 0) * PADX + arow] = vb[i].x;
                Bs0[(akb + 4 * i + 1) * PADX + arow] = vb[i].y;
                Bs0[(akb + 4 * i + 2) * PADX + arow] = vb[i].z;
                Bs0[(akb + 4 * i + 3) * PADX + arow] = vb[i].w;
            }
        } else {
            #pragma unroll
            for (int i = 0; i < 8; i++)
                *reinterpret_cast<float4*>(&Bs0[bkr * PADX + bnc + 4 * i]) = vb[i];
        }
    }
    __syncthreads();

    for (int t = 0; t < nt; ++t) {
        const int cur = t & 1;
        float* Asc = sm + cur * STGF;
        float* Bsc = Asc + TILEF;

        // prefetch next stage's globals into regs (overlaps with compute)
        if (t + 1 < nt) {
            const long long offA = (long long)(t + 1) * KST;
            const long long offB = BT ? offA : (long long)(t + 1) * KST * N;
            #pragma unroll
            for (int i = 0; i < 8; i++) {
                va[i] = *reinterpret_cast<const float4*>(ApA + offA + 4 * i);
                vb[i] = *reinterpret_cast<const float4*>(ApB + offB + 4 * i);
            }
        }

        // dual-pipe compute; per-SMSP stagger: warps 0-3 vs 4-7
        if (wid & 4) {
            mma_part(Asc, Bsc, wm, wn, r, c, acc);
            ffma_part(Asc, Bsc, wm, wn, r, c, acc);
        } else {
            ffma_part(Asc, Bsc, wm, wn, r, c, acc);
            mma_part(Asc, Bsc, wm, wn, r, c, acc);
        }

        // store next stage into the other buffer
        if (t + 1 < nt) {
            float* Asn = sm + (cur ^ 1) * STGF;
            float* Bsn = Asn + TILEF;
            #pragma unroll
            for (int i = 0; i < 8; i++) {
                Asn[(akb + 4 * i + 0) * PADX + arow] = va[i].x;
                Asn[(akb + 4 * i + 1) * PADX + arow] = va[i].y;
                Asn[(akb + 4 * i + 2) * PADX + arow] = va[i].z;
                Asn[(akb + 4 * i + 3) * PADX + arow] = va[i].w;
            }
            if (BT) {
                #pragma unroll
                for (int i = 0; i < 8; i++) {
                    Bsn[(akb + 4 * i + 0) * PADX + arow] = vb[i].x;
                    Bsn[(akb + 4 * i + 1) * PADX + arow] = vb[i].y;
                    Bsn[(akb + 4 * i + 2) * PADX + arow] = vb[i].z;
                    Bsn[(akb + 4 * i + 3) * PADX + arow] = vb[i].w;
                }
            } else {
                #pragma unroll
                for (int i = 0; i < 8; i++)
                    *reinterpret_cast<float4*>(&Bsn[bkr * PADX + bnc + 4 * i]) = vb[i];
            }
        }
        __syncthreads();
    }

    // Epilogue (mma fragment layout)
    #pragma unroll
    for (int mt = 0; mt < 2; mt++) {
        long long row0 = m0 + wm + mt * 16 + r;
        #pragma unroll
        for (int nt2 = 0; nt2 < 8; nt2++) {
            int col = wn + nt2 * 8 + 2 * c;
            float bx = 0.f, by = 0.f;
            if (bias) {
                float2 bb = *reinterpret_cast<const float2*>(bias + n0 + col);
                bx = bb.x; by = bb.y;
            }
            float2 o0 = make_float2(alpha * acc[mt][nt2][0] + bx,
                                    alpha * acc[mt][nt2][1] + by);
            float2 o1 = make_float2(alpha * acc[mt][nt2][2] + bx,
                                    alpha * acc[mt][nt2][3] + by);
            *reinterpret_cast<float2*>(C + row0 * N + n0 + col)       = o0;
            *reinterpret_cast<float2*>(C + (row0 + 8) * N + n0 + col) = o1;
        }
    }
}

// ---------------------------------------------------------------------------
// Small kernels
// ---------------------------------------------------------------------------
__global__ void transpose1024(const float* __restrict__ src, float* __restrict__ dst)
{
    __shared__ float t[32][33];
    int x = blockIdx.x * 32 + threadIdx.x;
    int y = blockIdx.y * 32 + threadIdx.y;
    #pragma unroll
    for (int i = 0; i < 4; i++)
        t[threadIdx.y + 8 * i][threadIdx.x] = src[(y + 8 * i) * HDIM + x];
    __syncthreads();
    x = blockIdx.y * 32 + threadIdx.x;
    y = blockIdx.x * 32 + threadIdx.y;
    #pragma unroll
    for (int i = 0; i < 4; i++)
        dst[(y + 8 * i) * HDIM + x] = t[threadIdx.x][threadIdx.y + 8 * i];
}

// u = Wk^T bq, two-phase (deterministic, high MLP)
__global__ void mv_u1(const float* __restrict__ Wk, const float* __restrict__ bq)
{
    int h  = (blockIdx.x & 3) * 256 + threadIdx.x;
    int oc = (blockIdx.x >> 2) * 32;
    float s = 0.f;
    #pragma unroll 8
    for (int i = 0; i < 32; i++)
        s += Wk[(long long)(oc + i) * HDIM + h] * bq[oc + i];
    g_upart[blockIdx.x >> 2][h] = s;
}
__global__ void mv_u2()
{
    int h = blockIdx.x * 256 + threadIdx.x;
    float s = 0.f;
    #pragma unroll
    for (int i = 0; i < 32; i++) s += g_upart[i][h];
    g_u[h] = s;
}

__global__ void mv_c(const float* __restrict__ X, const float* __restrict__ u,
                     float* __restrict__ c)
{
    int row = blockIdx.x * 8 + (threadIdx.x >> 5);
    int lane = threadIdx.x & 31;
    const float* xr = X + (long long)row * HDIM;
    float s = 0.f;
    for (int h = lane; h < HDIM; h += 32) s += xr[h] * u[h];
    #pragma unroll
    for (int o = 16; o > 0; o >>= 1) s += __shfl_xor_sync(0xffffffffu, s, o);
    if (lane == 0) c[row] = 0.125f * s;
}

__global__ void mv_d(const float* __restrict__ Wo, const float* __restrict__ bv,
                     const float* __restrict__ bo, float* __restrict__ d)
{
    int row = blockIdx.x * 8 + (threadIdx.x >> 5);
    int lane = threadIdx.x & 31;
    const float* wr = Wo + (long long)row * HDIM;
    float s = 0.f;
    for (int h = lane; h < HDIM; h += 32) s += wr[h] * bv[h];
    #pragma unroll
    for (int o = 16; o > 0; o >>= 1) s += __shfl_xor_sync(0xffffffffu, s, o);
    if (lane == 0) d[row] = s + bo[row];
}

__device__ __forceinline__ float warp_max(float v) {
    #pragma unroll
    for (int o = 16; o > 0; o >>= 1) v = fmaxf(v, __shfl_xor_sync(0xffffffffu, v, o));
    return v;
}
__device__ __forceinline__ float warp_sum(float v) {
    #pragma unroll
    for (int o = 16; o > 0; o >>= 1) v += __shfl_xor_sync(0xffffffffu, v, o);
    return v;
}

__global__ __launch_bounds__(256)
void softmax_rows(float* __restrict__ S)
{
    const int tid = threadIdx.x;
    float* rp = S + (size_t)blockIdx.x * SDIM;

    __shared__ float red[8];

    float v[16];
    float mx = -1e30f;
    #pragma unroll
    for (int i = 0; i < 16; i++) {
        v[i] = rp[tid + i * 256];
        mx = fmaxf(mx, v[i]);
    }
    mx = warp_max(mx);
    if ((tid & 31) == 0) red[tid >> 5] = mx;
    __syncthreads();
    {
        float t = (tid < 8) ? red[tid] : -1e30f;
        t = warp_max(t);
        if (tid == 0) red[0] = t;
    }
    __syncthreads();
    mx = red[0];
    __syncthreads();

    float sum = 0.f;
    #pragma unroll
    for (int i = 0; i < 16; i++) {
        v[i] = __expf(v[i] - mx);
        sum += v[i];
    }
    sum = warp_sum(sum);
    if ((tid & 31) == 0) red[tid >> 5] = sum;
    __syncthreads();
    {
        float t = (tid < 8) ? red[tid] : 0.f;
        t = warp_sum(t);
        if (tid == 0) red[0] = t;
    }
    __syncthreads();
    const float inv = 1.f / red[0];

    #pragma unroll
    for (int i = 0; i < 16; i++)
        rp[tid + i * 256] = v[i] * inv;
}

// ---------------------------------------------------------------------------
// Launch. Algebra (validated rounds 10-12):
//   scores ~ (x_i^T G x_j)/8 + c_j,  G = Wq^T Wk, c = 0.125 X (Wk^T bq)
//   out = (P X) H^T + d,  H = Wo Wv, d = Wo bv + bo
// ---------------------------------------------------------------------------
extern "C" void kernel_launch(void* const* d_in, const int* in_sizes, int n_in,
                              void* d_out, int out_size)
{
    const float* x  = (const float*)d_in[0];
    const float* Wq = (const float*)d_in[1];
    const float* bq = (const float*)d_in[2];
    const float* Wk = (const float*)d_in[3];
    const float* Wv = (const float*)d_in[5];
    const float* bv = (const float*)d_in[6];
    const float* Wo = (const float*)d_in[7];
    const float* bo = (const float*)d_in[8];
    float* out = (float*)d_out;

    cudaFuncSetAttribute(hgemm<true>,  cudaFuncAttributeMaxDynamicSharedMemorySize, SMEM_BYTES);
    cudaFuncSetAttribute(hgemm<false>, cudaFuncAttributeMaxDynamicSharedMemorySize, SMEM_BYTES);

    const dim3 blk(256);
    const long long SH = (long long)SDIM * HDIM;
    const long long SS = (long long)SDIM * SDIM;

    // Precomputes
    transpose1024<<<dim3(32, 32), dim3(32, 8)>>>(Wq, g_wqt);
    hgemm<false><<<dim3(8, 8), blk, SMEM_BYTES>>>(g_wqt, Wk, nullptr, g_G,
        HDIM, HDIM, HDIM, 1.f, 0, 0, 0, 0);
    hgemm<false><<<dim3(8, 8), blk, SMEM_BYTES>>>(Wo, Wv, nullptr, g_H,
        HDIM, HDIM, HDIM, 1.f, 0, 0, 0, 0);
    mv_u1<<<128, 256>>>(Wk, bq);
    mv_u2<<<4, 256>>>();
    mv_c<<<MDIM / 8, 256>>>(x, g_u, g_c);
    mv_d<<<HDIM / 8, 256>>>(Wo, bv, bo, g_d);

    // T = X * G   [8192 x 1024]
    hgemm<false><<<dim3(8, 64), blk, SMEM_BYTES>>>(x, g_G, nullptr, g_T,
        MDIM, HDIM, HDIM, 1.f, 0, 0, 0, 0);

    // scores = 0.125 * (T X^T) + c_j   (per batch)
    hgemm<true><<<dim3(32, 32, BDIM), blk, SMEM_BYTES>>>(g_T, x, g_c, g_s,
        SDIM, SDIM, HDIM, 0.125f, SH, SH, SS, SDIM);

    // softmax rows (in place)
    softmax_rows<<<BDIM * SDIM, 256>>>(g_s);

    // U = P * X   (per batch)
    hgemm<false><<<dim3(8, 32, BDIM), blk, SMEM_BYTES>>>(g_s, x, nullptr, g_U,
        SDIM, HDIM, SDIM, 1.f, SS, SH, SH, 0);

    // out = U * H^T + d
    hgemm<true><<<dim3(8, 64), blk, SMEM_BYTES>>>(g_U, g_H, g_d, out,
        MDIM, HDIM, HDIM, 1.f, 0, 0, 0, 0);
}

// round 15
// speedup vs baseline: 1.0097x; 1.0097x over previous
#include <cuda_runtime.h>
#include <math.h>
#include <stdint.h>

// Problem shape: B=2, S=4096, H=1024, M=B*S=8192
#define BDIM 2
#define SDIM 4096
#define HDIM 1024
#define MDIM 8192

#define KST 64            // K per smem stage
#define KFF 32            // k-range on FFMA pipe (rebalanced: tensor had slack)
#define PADX 132          // floats per smem k-row
#define TILEF (KST * PADX)         // floats per tile (A or B)
#define STGF (2 * TILEF)           // floats per stage (A + B)
#define SMEM_BYTES (2 * STGF * 4)  // 2 stages = 135168 B

// Scratch
__device__ float g_wqt[(size_t)HDIM * HDIM];   // Wq^T
__device__ float g_G[(size_t)HDIM * HDIM];     // Wq^T * Wk
__device__ float g_H[(size_t)HDIM * HDIM];     // Wo * Wv
__device__ float g_T[(size_t)MDIM * HDIM];     // X * G
__device__ float g_U[(size_t)MDIM * HDIM];     // P * X
__device__ float g_s[(size_t)BDIM * SDIM * SDIM];
__device__ float g_c[MDIM];
__device__ float g_u[HDIM];
__device__ float g_upart[32][HDIM];
__device__ float g_d[HDIM];

// ---------------- helpers ----------------
__device__ __forceinline__ uint32_t tf32hi(float x) {
    uint32_t y;
    asm("cvt.rna.tf32.f32 %0, %1;" : "=r"(y) : "f"(x));
    return y;
}
__device__ __forceinline__ float u2f(uint32_t u) { return __uint_as_float(u); }

__device__ __forceinline__ void mma8(float* d, const uint32_t* a, uint32_t b0, uint32_t b1) {
    asm volatile(
        "mma.sync.aligned.m16n8k8.row.col.f32.tf32.tf32.f32 "
        "{%0,%1,%2,%3}, {%4,%5,%6,%7}, {%8,%9}, {%0,%1,%2,%3};\n"
        : "+f"(d[0]), "+f"(d[1]), "+f"(d[2]), "+f"(d[3])
        : "r"(a[0]), "r"(a[1]), "r"(a[2]), "r"(a[3]), "r"(b0), "r"(b1));
}

// ---------------------------------------------------------------------------
// FFMA part: k in [0, KFF). mma-fragment-layout accumulators.
// Warp tile 32(m) x 64(n). Lane (r=lane>>2, c=lane&3) owns rows {base+r, +8},
// cols {2c, 2c+1} of each 16x8 mma tile.
// ---------------------------------------------------------------------------
__device__ __forceinline__ void ffma_part(
    const float* __restrict__ As, const float* __restrict__ Bs,
    int wm, int wn, int r, int c, float acc[2][8][4])
{
    #pragma unroll 4
    for (int k = 0; k < KFF; ++k) {
        const float* ar = As + k * PADX + wm + r;
        const float* br = Bs + k * PADX + wn + 2 * c;
        float a00 = ar[0],  a01 = ar[8];
        float a10 = ar[16], a11 = ar[24];
        #pragma unroll
        for (int nt = 0; nt < 8; nt++) {
            float2 b = *reinterpret_cast<const float2*>(br + 8 * nt);
            acc[0][nt][0] += a00 * b.x; acc[0][nt][1] += a00 * b.y;
            acc[0][nt][2] += a01 * b.x; acc[0][nt][3] += a01 * b.y;
            acc[1][nt][0] += a10 * b.x; acc[1][nt][1] += a10 * b.y;
            acc[1][nt][2] += a11 * b.x; acc[1][nt][3] += a11 * b.y;
        }
    }
}

// ---------------------------------------------------------------------------
// MMA part: k in [KFF, KST), 4 chunks of k8, tf32x3 (hh + hl + lh).
// ---------------------------------------------------------------------------
__device__ __forceinline__ void mma_part(
    const float* __restrict__ As, const float* __restrict__ Bs,
    int wm, int wn, int r, int c, float acc[2][8][4])
{
    #pragma unroll
    for (int ks = 0; ks < (KST - KFF) / 8; ++ks) {
        const int k = KFF + ks * 8;
        const float* a0 = As + (k + c) * PADX + wm + r;
        const float* a1 = As + (k + c + 4) * PADX + wm + r;
        uint32_t ah[2][4], al[2][4];
        #pragma unroll
        for (int mt = 0; mt < 2; mt++) {
            float s0 = a0[mt * 16], s1 = a0[mt * 16 + 8];
            float s2 = a1[mt * 16], s3 = a1[mt * 16 + 8];
            ah[mt][0] = tf32hi(s0); ah[mt][1] = tf32hi(s1);
            ah[mt][2] = tf32hi(s2); ah[mt][3] = tf32hi(s3);
            al[mt][0] = tf32hi(s0 - u2f(ah[mt][0]));
            al[mt][1] = tf32hi(s1 - u2f(ah[mt][1]));
            al[mt][2] = tf32hi(s2 - u2f(ah[mt][2]));
            al[mt][3] = tf32hi(s3 - u2f(ah[mt][3]));
        }
        const float* b0p = Bs + (k + c) * PADX + wn + r;
        const float* b1p = Bs + (k + c + 4) * PADX + wn + r;
        #pragma unroll
        for (int nt = 0; nt < 8; nt++) {
            float t0 = b0p[8 * nt], t1 = b1p[8 * nt];
            uint32_t bh0 = tf32hi(t0), bh1 = tf32hi(t1);
            uint32_t bl0 = tf32hi(t0 - u2f(bh0)), bl1 = tf32hi(t1 - u2f(bh1));
            #pragma unroll
            for (int mt = 0; mt < 2; mt++) {
                mma8(acc[mt][nt], ah[mt], bh0, bh1);  // hi*hi
                mma8(acc[mt][nt], ah[mt], bl0, bl1);  // hi*lo
                mma8(acc[mt][nt], al[mt], bh0, bh1);  // lo*hi
            }
        }
    }
}

// ---------------------------------------------------------------------------
// Hybrid dual-pipe GEMM, register-prefetch double-buffered smem.
// BT=true: B is [N,K] (NT); BT=false: B is [K,N] (NN).
// CTA tile 128x128, 256 threads, 8 warps (4m x 2n of 32x64 warp tiles).
// Pipe stagger by (wid & 4): each SMSP holds one ffma-phase and one
// mma-phase warp at all times.
// ---------------------------------------------------------------------------
template <bool BT>
__global__ __launch_bounds__(256, 1)
void hgemm(const float* __restrict__ A, const float* __restrict__ B,
           const float* __restrict__ bias, float* __restrict__ C,
           int M, int N, int K, float alpha,
           long long sA, long long sB, long long sC, long long sBias)
{
    extern __shared__ float sm[];

    A += (long long)blockIdx.z * sA;
    B += (long long)blockIdx.z * sB;
    C += (long long)blockIdx.z * sC;
    if (bias) bias += (long long)blockIdx.z * sBias;

    const int tid  = threadIdx.x;
    const int lane = tid & 31;
    const int wid  = tid >> 5;
    const int r = lane >> 2;
    const int c = lane & 3;
    const int wm = (wid & 3) * 32;
    const int wn = (wid >> 2) * 64;

    const long long m0 = (long long)blockIdx.y * 128;
    const long long n0 = (long long)blockIdx.x * 128;

    // loader mappings
    const int arow = tid >> 1;          // 0..127
    const int akb  = (tid & 1) * 32;    // 0 or 32
    const int bkr  = tid >> 2;          // 0..63 (NN B rows)
    const int bnc  = (tid & 3) * 32;    // 0..96

    const float* ApA = A + (m0 + arow) * K + akb;
    const float* ApB = BT ? (B + (n0 + arow) * K + akb)
                          : (B + (long long)bkr * N + n0 + bnc);

    float acc[2][8][4];
    #pragma unroll
    for (int i = 0; i < 2; i++)
        #pragma unroll
        for (int j = 0; j < 8; j++)
            #pragma unroll
            for (int q = 0; q < 4; q++) acc[i][j][q] = 0.f;

    const int nt = K / KST;
    float4 va[8], vb[8];

    // prologue: stage 0 -> regs -> smem buffer 0
    #pragma unroll
    for (int i = 0; i < 8; i++) {
        va[i] = *reinterpret_cast<const float4*>(ApA + 4 * i);
        vb[i] = *reinterpret_cast<const float4*>(ApB + 4 * i);
    }
    {
        float* As0 = sm;
        float* Bs0 = sm + TILEF;
        #pragma unroll
        for (int i = 0; i < 8; i++) {
            As0[(akb + 4 * i + 0) * PADX + arow] = va[i].x;
            As0[(akb + 4 * i + 1) * PADX + arow] = va[i].y;
            As0[(akb + 4 * i + 2) * PADX + arow] = va[i].z;
            As0[(akb + 4 * i + 3) * PADX + arow] = va[i].w;
        }
        if (BT) {
            #pragma unroll
            for (int i = 0; i < 8; i++) {
                Bs0[(akb + 4 * i + 0) * PADX + arow] = vb[i].x;
                Bs0[(akb + 4 * i + 1) * PADX + arow] = vb[i].y;
                Bs0[(akb + 4 * i + 2) * PADX + arow] = vb[i].z;
                Bs0[(akb + 4 * i + 3) * PADX + arow] = vb[i].w;
            }
        } else {
            #pragma unroll
            for (int i = 0; i < 8; i++)
                *reinterpret_cast<float4*>(&Bs0[bkr * PADX + bnc + 4 * i]) = vb[i];
        }
    }
    __syncthreads();

    for (int t = 0; t < nt; ++t) {
        const int cur = t & 1;
        float* Asc = sm + cur * STGF;
        float* Bsc = Asc + TILEF;

        // prefetch next stage's globals into regs (overlaps with compute)
        if (t + 1 < nt) {
            const long long offA = (long long)(t + 1) * KST;
            const long long offB = BT ? offA : (long long)(t + 1) * KST * N;
            #pragma unroll
            for (int i = 0; i < 8; i++) {
                va[i] = *reinterpret_cast<const float4*>(ApA + offA + 4 * i);
                vb[i] = *reinterpret_cast<const float4*>(ApB + offB + 4 * i);
            }
        }

        // dual-pipe compute; per-SMSP stagger: warps 0-3 vs 4-7
        if (wid & 4) {
            mma_part(Asc, Bsc, wm, wn, r, c, acc);
            ffma_part(Asc, Bsc, wm, wn, r, c, acc);
        } else {
            ffma_part(Asc, Bsc, wm, wn, r, c, acc);
            mma_part(Asc, Bsc, wm, wn, r, c, acc);
        }

        // store next stage into the other buffer
        if (t + 1 < nt) {
            float* Asn = sm + (cur ^ 1) * STGF;
            float* Bsn = Asn + TILEF;
            #pragma unroll
            for (int i = 0; i < 8; i++) {
                Asn[(akb + 4 * i + 0) * PADX + arow] = va[i].x;
                Asn[(akb + 4 * i + 1) * PADX + arow] = va[i].y;
                Asn[(akb + 4 * i + 2) * PADX + arow] = va[i].z;
                Asn[(akb + 4 * i + 3) * PADX + arow] = va[i].w;
            }
            if (BT) {
                #pragma unroll
                for (int i = 0; i < 8; i++) {
                    Bsn[(akb + 4 * i + 0) * PADX + arow] = vb[i].x;
                    Bsn[(akb + 4 * i + 1) * PADX + arow] = vb[i].y;
                    Bsn[(akb + 4 * i + 2) * PADX + arow] = vb[i].z;
                    Bsn[(akb + 4 * i + 3) * PADX + arow] = vb[i].w;
                }
            } else {
                #pragma unroll
                for (int i = 0; i < 8; i++)
                    *reinterpret_cast<float4*>(&Bsn[bkr * PADX + bnc + 4 * i]) = vb[i];
            }
        }
        __syncthreads();
    }

    // Epilogue (mma fragment layout)
    #pragma unroll
    for (int mt = 0; mt < 2; mt++) {
        long long row0 = m0 + wm + mt * 16 + r;
        #pragma unroll
        for (int nt2 = 0; nt2 < 8; nt2++) {
            int col = wn + nt2 * 8 + 2 * c;
            float bx = 0.f, by = 0.f;
            if (bias) {
                float2 bb = *reinterpret_cast<const float2*>(bias + n0 + col);
                bx = bb.x; by = bb.y;
            }
            float2 o0 = make_float2(alpha * acc[mt][nt2][0] + bx,
                                    alpha * acc[mt][nt2][1] + by);
            float2 o1 = make_float2(alpha * acc[mt][nt2][2] + bx,
                                    alpha * acc[mt][nt2][3] + by);
            *reinterpret_cast<float2*>(C + row0 * N + n0 + col)       = o0;
            *reinterpret_cast<float2*>(C + (row0 + 8) * N + n0 + col) = o1;
        }
    }
}

// ---------------------------------------------------------------------------
// Small kernels
// ---------------------------------------------------------------------------
__global__ void transpose1024(const float* __restrict__ src, float* __restrict__ dst)
{
    __shared__ float t[32][33];
    int x = blockIdx.x * 32 + threadIdx.x;
    int y = blockIdx.y * 32 + threadIdx.y;
    #pragma unroll
    for (int i = 0; i < 4; i++)
        t[threadIdx.y + 8 * i][threadIdx.x] = src[(y + 8 * i) * HDIM + x];
    __syncthreads();
    x = blockIdx.y * 32 + threadIdx.x;
    y = blockIdx.x * 32 + threadIdx.y;
    #pragma unroll
    for (int i = 0; i < 4; i++)
        dst[(y + 8 * i) * HDIM + x] = t[threadIdx.x][threadIdx.y + 8 * i];
}

// u = Wk^T bq, two-phase (deterministic, high MLP)
__global__ void mv_u1(const float* __restrict__ Wk, const float* __restrict__ bq)
{
    int h  = (blockIdx.x & 3) * 256 + threadIdx.x;
    int oc = (blockIdx.x >> 2) * 32;
    float s = 0.f;
    #pragma unroll 8
    for (int i = 0; i < 32; i++)
        s += Wk[(long long)(oc + i) * HDIM + h] * bq[oc + i];
    g_upart[blockIdx.x >> 2][h] = s;
}
__global__ void mv_u2()
{
    int h = blockIdx.x * 256 + threadIdx.x;
    float s = 0.f;
    #pragma unroll
    for (int i = 0; i < 32; i++) s += g_upart[i][h];
    g_u[h] = s;
}

__global__ void mv_c(const float* __restrict__ X, const float* __restrict__ u,
                     float* __restrict__ c)
{
    int row = blockIdx.x * 8 + (threadIdx.x >> 5);
    int lane = threadIdx.x & 31;
    const float* xr = X + (long long)row * HDIM;
    float s = 0.f;
    for (int h = lane; h < HDIM; h += 32) s += xr[h] * u[h];
    #pragma unroll
    for (int o = 16; o > 0; o >>= 1) s += __shfl_xor_sync(0xffffffffu, s, o);
    if (lane == 0) c[row] = 0.125f * s;
}

__global__ void mv_d(const float* __restrict__ Wo, const float* __restrict__ bv,
                     const float* __restrict__ bo, float* __restrict__ d)
{
    int row = blockIdx.x * 8 + (threadIdx.x >> 5);
    int lane = threadIdx.x & 31;
    const float* wr = Wo + (long long)row * HDIM;
    float s = 0.f;
    for (int h = lane; h < HDIM; h += 32) s += wr[h] * bv[h];
    #pragma unroll
    for (int o = 16; o > 0; o >>= 1) s += __shfl_xor_sync(0xffffffffu, s, o);
    if (lane == 0) d[row] = s + bo[row];
}

__device__ __forceinline__ float warp_max(float v) {
    #pragma unroll
    for (int o = 16; o > 0; o >>= 1) v = fmaxf(v, __shfl_xor_sync(0xffffffffu, v, o));
    return v;
}
__device__ __forceinline__ float warp_sum(float v) {
    #pragma unroll
    for (int o = 16; o > 0; o >>= 1) v += __shfl_xor_sync(0xffffffffu, v, o);
    return v;
}

__global__ __launch_bounds__(256)
void softmax_rows(float* __restrict__ S)
{
    const int tid = threadIdx.x;
    float* rp = S + (size_t)blockIdx.x * SDIM;

    __shared__ float red[8];

    float v[16];
    float mx = -1e30f;
    #pragma unroll
    for (int i = 0; i < 16; i++) {
        v[i] = rp[tid + i * 256];
        mx = fmaxf(mx, v[i]);
    }
    mx = warp_max(mx);
    if ((tid & 31) == 0) red[tid >> 5] = mx;
    __syncthreads();
    {
        float t = (tid < 8) ? red[tid] : -1e30f;
        t = warp_max(t);
        if (tid == 0) red[0] = t;
    }
    __syncthreads();
    mx = red[0];
    __syncthreads();

    float sum = 0.f;
    #pragma unroll
    for (int i = 0; i < 16; i++) {
        v[i] = __expf(v[i] - mx);
        sum += v[i];
    }
    sum = warp_sum(sum);
    if ((tid & 31) == 0) red[tid >> 5] = sum;
    __syncthreads();
    {
        float t = (tid < 8) ? red[tid] : 0.f;
        t = warp_sum(t);
        if (tid == 0) red[0] = t;
    }
    __syncthreads();
    const float inv = 1.f / red[0];

    #pragma unroll
    for (int i = 0; i < 16; i++)
        rp[tid + i * 256] = v[i] * inv;
}

// ---------------------------------------------------------------------------
// Launch. Algebra (validated rounds 10-14):
//   scores ~ (x_i^T G x_j)/8 + c_j,  G = Wq^T Wk, c = 0.125 X (Wk^T bq)
//   out = (P X) H^T + d,  H = Wo Wv, d = Wo bv + bo
// ---------------------------------------------------------------------------
extern "C" void kernel_launch(void* const* d_in, const int* in_sizes, int n_in,
                              void* d_out, int out_size)
{
    const float* x  = (const float*)d_in[0];
    const float* Wq = (const float*)d_in[1];
    const float* bq = (const float*)d_in[2];
    const float* Wk = (const float*)d_in[3];
    const float* Wv = (const float*)d_in[5];
    const float* bv = (const float*)d_in[6];
    const float* Wo = (const float*)d_in[7];
    const float* bo = (const float*)d_in[8];
    float* out = (float*)d_out;

    cudaFuncSetAttribute(hgemm<true>,  cudaFuncAttributeMaxDynamicSharedMemorySize, SMEM_BYTES);
    cudaFuncSetAttribute(hgemm<false>, cudaFuncAttributeMaxDynamicSharedMemorySize, SMEM_BYTES);

    const dim3 blk(256);
    const long long SH = (long long)SDIM * HDIM;
    const long long SS = (long long)SDIM * SDIM;

    // Precomputes
    transpose1024<<<dim3(32, 32), dim3(32, 8)>>>(Wq, g_wqt);
    hgemm<false><<<dim3(8, 8), blk, SMEM_BYTES>>>(g_wqt, Wk, nullptr, g_G,
        HDIM, HDIM, HDIM, 1.f, 0, 0, 0, 0);
    hgemm<false><<<dim3(8, 8), blk, SMEM_BYTES>>>(Wo, Wv, nullptr, g_H,
        HDIM, HDIM, HDIM, 1.f, 0, 0, 0, 0);
    mv_u1<<<128, 256>>>(Wk, bq);
    mv_u2<<<4, 256>>>();
    mv_c<<<MDIM / 8, 256>>>(x, g_u, g_c);
    mv_d<<<HDIM / 8, 256>>>(Wo, bv, bo, g_d);

    // T = X * G   [8192 x 1024]
    hgemm<false><<<dim3(8, 64), blk, SMEM_BYTES>>>(x, g_G, nullptr, g_T,
        MDIM, HDIM, HDIM, 1.f, 0, 0, 0, 0);

    // scores = 0.125 * (T X^T) + c_j   (per batch)
    hgemm<true><<<dim3(32, 32, BDIM), blk, SMEM_BYTES>>>(g_T, x, g_c, g_s,
        SDIM, SDIM, HDIM, 0.125f, SH, SH, SS, SDIM);

    // softmax rows (in place)
    softmax_rows<<<BDIM * SDIM, 256>>>(g_s);

    // U = P * X   (per batch)
    hgemm<false><<<dim3(8, 32, BDIM), blk, SMEM_BYTES>>>(g_s, x, nullptr, g_U,
        SDIM, HDIM, SDIM, 1.f, SS, SH, SH, 0);

    // out = U * H^T + d
    hgemm<true><<<dim3(8, 64), blk, SMEM_BYTES>>>(g_U, g_H, g_d, out,
        MDIM, HDIM, HDIM, 1.f, 0, 0, 0, 0);
}